// round 7
// baseline (speedup 1.0000x reference)
#include <cuda_runtime.h>
#include <math_constants.h>

// Warp-per-row fused multi-teacher KD loss.
// R6: packed f32x2 hot loop (mul/add/fma.rn.f32x2) processing element pairs;
//     scalar MUFU EX2; m1 scalar. Tail kernels unchanged from R5.

namespace {
constexpr int NB = 8192;
constexpr int NC = 1000;
constexpr int NV4 = 250;
constexpr int NBLK = NB / 8;                       // 1024 row_kernel blocks
constexpr int RBLK = 32;
constexpr float L2E   = 1.4426950408889634f;       // log2(e)
constexpr float C20   = 1.4426950408889634f / 20.0f;
constexpr float CTHR  = 1.4426950408889634f / 6.0f;
}

__device__ float g_rowbuf[NB * 16];
__device__ float g_bmin[NBLK];
__device__ float g_bmax[NBLK];
__device__ float g_partial[RBLK];

using u64 = unsigned long long;
__device__ __forceinline__ u64 pk2(float lo, float hi) {
    u64 r; asm("mov.b64 %0, {%1, %2};" : "=l"(r) : "f"(lo), "f"(hi)); return r;
}
__device__ __forceinline__ void upk2(u64 v, float& lo, float& hi) {
    asm("mov.b64 {%0, %1}, %2;" : "=f"(lo), "=f"(hi) : "l"(v));
}
__device__ __forceinline__ u64 mul2(u64 a, u64 b) {
    u64 r; asm("mul.rn.f32x2 %0, %1, %2;" : "=l"(r) : "l"(a), "l"(b)); return r;
}
__device__ __forceinline__ u64 add2(u64 a, u64 b) {
    u64 r; asm("add.rn.f32x2 %0, %1, %2;" : "=l"(r) : "l"(a), "l"(b)); return r;
}
__device__ __forceinline__ u64 fma2(u64 a, u64 b, u64 c) {
    u64 r; asm("fma.rn.f32x2 %0, %1, %2, %3;" : "=l"(r) : "l"(a), "l"(b), "l"(c)); return r;
}

__global__ __launch_bounds__(256, 4) void row_kernel(
    const float* __restrict__ o1, const float* __restrict__ o2,
    const float* __restrict__ o3, const float* __restrict__ o4,
    const float* __restrict__ os, const int* __restrict__ tgts)
{
    __shared__ float s_min[8], s_max[8];

    const int lane = threadIdx.x & 31;
    const int wid  = threadIdx.x >> 5;
    const int row  = blockIdx.x * 8 + wid;
    const size_t base = (size_t)row * NC;

    const float4* A  = reinterpret_cast<const float4*>(o1 + base) + lane;
    const float4* B  = reinterpret_cast<const float4*>(o2 + base) + lane;
    const float4* C  = reinterpret_cast<const float4*>(o3 + base) + lane;
    const float4* D4 = reinterpret_cast<const float4*>(o4 + base) + lane;
    const float4* S  = reinterpret_cast<const float4*>(os + base) + lane;

    const u64 C202  = pk2(C20,  C20);
    const u64 L2E2  = pk2(L2E,  L2E);
    const u64 QTR2  = pk2(0.25f, 0.25f);
    const u64 NEG12 = pk2(-1.0f, -1.0f);

    u64 E2[5], D2[5];
#pragma unroll
    for (int b = 0; b < 5; b++) { E2[b] = 0ull; D2[b] = 0ull; }   // (0.f,0.f)
    u64 Es1_2 = 0ull, EsT_2 = 0ull;
    float m1[5];
#pragma unroll
    for (int b = 0; b < 5; b++) m1[b] = -CUDART_INF_F;

    auto body = [&](float4 va, float4 vb, float4 vc, float4 vd, float4 vs) {
#pragma unroll
        for (int h = 0; h < 2; h++) {
            const float a0 = h ? va.z : va.x, a1 = h ? va.w : va.y;
            const float b0 = h ? vb.z : vb.x, b1 = h ? vb.w : vb.y;
            const float c0 = h ? vc.z : vc.x, c1 = h ? vc.w : vc.y;
            const float d0 = h ? vd.z : vd.x, d1 = h ? vd.w : vd.y;
            const float s0 = h ? vs.z : vs.x, s1 = h ? vs.w : vs.y;

            const u64 zs2 = pk2(s0, s1);
            float xl, xh;

            // student: sum e^zs and e^(zs/20)
            upk2(mul2(zs2, L2E2), xl, xh);
            Es1_2 = add2(Es1_2, pk2(exp2f(xl), exp2f(xh)));
            upk2(mul2(zs2, C202), xl, xh);
            EsT_2 = add2(EsT_2, pk2(exp2f(xl), exp2f(xh)));

            // mimic = avg of 4 teachers (packed)
            const u64 za2 = pk2(a0, a1), zb2 = pk2(b0, b1);
            const u64 zc2 = pk2(c0, c1), zd2 = pk2(d0, d1);
            const u64 zm2 = mul2(add2(add2(za2, zb2), add2(zc2, zd2)), QTR2);
            float m0, m1v; upk2(zm2, m0, m1v);

            const u64 zz2[5]  = { za2, zb2, zc2, zd2, zm2 };
            const float zl[5] = { a0, b0, c0, d0, m0 };
            const float zh[5] = { a1, b1, c1, d1, m1v };
#pragma unroll
            for (int b = 0; b < 5; b++) {
                upk2(mul2(zz2[b], C202), xl, xh);
                const u64 e2 = pk2(exp2f(xl), exp2f(xh));
                E2[b] = add2(E2[b], e2);
                const u64 dz = fma2(zs2, NEG12, zz2[b]);   // z - zs (exact)
                D2[b] = fma2(e2, dz, D2[b]);
                m1[b] = fmaxf(m1[b], zl[b]);
                m1[b] = fmaxf(m1[b], zh[b]);
            }
        }
    };

#pragma unroll 1
    for (int k = 0; k < 7; k++) {
        const int o = k * 32;
        body(A[o], B[o], C[o], D4[o], S[o]);
    }
    if (lane < NV4 - 224)                          // tail: idx = 224+lane < 250
        body(A[224], B[224], C[224], D4[224], S[224]);

    // collapse packed accumulators
    float E[5], D[5], Es1, EsT;
    {
        float lo, hi;
#pragma unroll
        for (int b = 0; b < 5; b++) {
            upk2(E2[b], lo, hi); E[b] = lo + hi;
            upk2(D2[b], lo, hi); D[b] = lo + hi;
        }
        upk2(Es1_2, lo, hi); Es1 = lo + hi;
        upk2(EsT_2, lo, hi); EsT = lo + hi;
    }

    // target logits: lane 0 gathers (L1/L2 hot), then broadcast
    const int tg = tgts[row];
    float g0 = 0, g1 = 0, g2 = 0, g3 = 0, zst = 0;
    if (lane == 0) {
        g0 = o1[base + tg]; g1 = o2[base + tg];
        g2 = o3[base + tg]; g3 = o4[base + tg];
        zst = os[base + tg];
    }

    // warp reduction: 12 sums + 5 maxes
#pragma unroll
    for (int off = 16; off; off >>= 1) {
#pragma unroll
        for (int b = 0; b < 5; b++) {
            E[b]  += __shfl_xor_sync(0xffffffffu, E[b],  off);
            D[b]  += __shfl_xor_sync(0xffffffffu, D[b],  off);
            m1[b]  = fmaxf(m1[b], __shfl_xor_sync(0xffffffffu, m1[b], off));
        }
        Es1 += __shfl_xor_sync(0xffffffffu, Es1, off);
        EsT += __shfl_xor_sync(0xffffffffu, EsT, off);
    }

    g0  = __shfl_sync(0xffffffffu, g0, 0);
    g1  = __shfl_sync(0xffffffffu, g1, 0);
    g2  = __shfl_sync(0xffffffffu, g2, 0);
    g3  = __shfl_sync(0xffffffffu, g3, 0);
    zst = __shfl_sync(0xffffffffu, zst, 0);
    const float g4 = ((g0 + g1) + (g2 + g3)) * 0.25f;
    const float g[5] = { g0, g1, g2, g3, g4 };

    // rare re-pass: only when some branch's max equals its target logit
    float m2[5] = { -CUDART_INF_F, -CUDART_INF_F, -CUDART_INF_F,
                    -CUDART_INF_F, -CUDART_INF_F };
    bool need = false;
#pragma unroll
    for (int b = 0; b < 5; b++) need |= (m1[b] == g[b]);
    if (need) {                                   // warp-uniform
        float n1[5], n2[5];
#pragma unroll
        for (int b = 0; b < 5; b++) { n1[b] = -CUDART_INF_F; n2[b] = -CUDART_INF_F; }
        auto top2 = [&](float4 va, float4 vb, float4 vc, float4 vd) {
            const float za[4] = { va.x, va.y, va.z, va.w };
            const float zb[4] = { vb.x, vb.y, vb.z, vb.w };
            const float zc[4] = { vc.x, vc.y, vc.z, vc.w };
            const float zd[4] = { vd.x, vd.y, vd.z, vd.w };
#pragma unroll
            for (int j = 0; j < 4; j++) {
                const float zm = ((za[j] + zb[j]) + (zc[j] + zd[j])) * 0.25f;
                const float zz[5] = { za[j], zb[j], zc[j], zd[j], zm };
#pragma unroll
                for (int b = 0; b < 5; b++) {
                    const float z = zz[b];
                    n2[b] = fmaxf(n2[b], fminf(n1[b], z));
                    n1[b] = fmaxf(n1[b], z);
                }
            }
        };
#pragma unroll 1
        for (int k = 0; k < 7; k++) {
            const int o = k * 32;
            top2(A[o], B[o], C[o], D4[o]);
        }
        if (lane < NV4 - 224)
            top2(A[224], B[224], C[224], D4[224]);
#pragma unroll
        for (int off = 16; off; off >>= 1) {
#pragma unroll
            for (int b = 0; b < 5; b++) {
                float a1 = __shfl_xor_sync(0xffffffffu, n1[b], off);
                float a2 = __shfl_xor_sync(0xffffffffu, n2[b], off);
                n2[b] = fmaxf(n2[b], fminf(n1[b], a1));
                n2[b] = fmaxf(n2[b], a2);
                n1[b] = fmaxf(n1[b], a1);
            }
        }
#pragma unroll
        for (int b = 0; b < 5; b++) m2[b] = n2[b];
    }

    if (lane == 0) {
        float te[5], ts = 0.0f;
#pragma unroll
        for (int b = 0; b < 5; b++) {
            const float mg = (m1[b] == g[b]) ? (m1[b] - m2[b]) : 0.0f;
            te[b] = exp2f(mg * CTHR);
            ts += te[b];
        }
        const float invts = 1.0f / ts;

        const float CE   = __logf(Es1) - zst;
        const float lseT = __logf(EsT);

        float rb[16];
        rb[0] = CE;
#pragma unroll
        for (int b = 0; b < 5; b++) {
            const float iE = 1.0f / E[b];
            const float KD = 20.0f * D[b] * iE + 400.0f * (lseT - __logf(E[b]));
            rb[1 + b]  = te[b] * invts;
            rb[6 + b]  = g[b];
            rb[11 + b] = KD;
        }
        float4* out4 = reinterpret_cast<float4*>(g_rowbuf + (size_t)row * 16);
        out4[0] = make_float4(rb[0],  rb[1],  rb[2],  rb[3]);
        out4[1] = make_float4(rb[4],  rb[5],  rb[6],  rb[7]);
        out4[2] = make_float4(rb[8],  rb[9],  rb[10], rb[11]);
        out4[3] = make_float4(rb[12], rb[13], rb[14], rb[15]);

        s_min[wid] = fminf(fminf(g[0], g[1]), fminf(g[2], g[3]));
        s_max[wid] = fmaxf(fmaxf(m1[0], m1[1]), fmaxf(m1[2], m1[3]));
    }
    __syncthreads();
    if (threadIdx.x == 0) {
        float mn = s_min[0], mx = s_max[0];
#pragma unroll
        for (int w = 1; w < 8; w++) { mn = fminf(mn, s_min[w]); mx = fmaxf(mx, s_max[w]); }
        g_bmin[blockIdx.x] = mn;
        g_bmax[blockIdx.x] = mx;
    }
}

__global__ __launch_bounds__(256) void reduce_kernel() {
    __shared__ float sm[8], sx[8], rs[8];
    const int t = threadIdx.x, lane = t & 31, wid = t >> 5;

    float mn = CUDART_INF_F, mx = -CUDART_INF_F;
#pragma unroll
    for (int i = 0; i < NBLK / 256; i++) {
        mn = fminf(mn, g_bmin[t + i * 256]);
        mx = fmaxf(mx, g_bmax[t + i * 256]);
    }
#pragma unroll
    for (int off = 16; off; off >>= 1) {
        mn = fminf(mn, __shfl_xor_sync(0xffffffffu, mn, off));
        mx = fmaxf(mx, __shfl_xor_sync(0xffffffffu, mx, off));
    }
    if (lane == 0) { sm[wid] = mn; sx[wid] = mx; }
    __syncthreads();
    float Cv = sm[0], Mv = sx[0];
#pragma unroll
    for (int w = 1; w < 8; w++) { Cv = fminf(Cv, sm[w]); Mv = fmaxf(Mv, sx[w]); }

    const float shift = (Cv < 0.0f) ? (-Cv + 1e-5f) : 0.0f;
    const float inv   = 1.0f / (Mv + shift);

    const int row = blockIdx.x * 256 + t;
    const float* r = g_rowbuf + (size_t)row * 16;
    float4 q0 = *reinterpret_cast<const float4*>(r);
    float4 q1 = *reinterpret_cast<const float4*>(r + 4);
    float4 q2 = *reinterpret_cast<const float4*>(r + 8);
    float4 q3 = *reinterpret_cast<const float4*>(r + 12);
    const float a[16] = { q0.x,q0.y,q0.z,q0.w, q1.x,q1.y,q1.z,q1.w,
                          q2.x,q2.y,q2.z,q2.w, q3.x,q3.y,q3.z,q3.w };
    const float CE = a[0];
    float loss = 0.0f;
#pragma unroll
    for (int b = 0; b < 5; b++) {
        const float w2 = (a[6 + b] + shift) * inv;
        loss += a[1 + b] * ((1.0f - w2) * CE + w2 * a[11 + b]);
    }
#pragma unroll
    for (int off = 16; off; off >>= 1)
        loss += __shfl_xor_sync(0xffffffffu, loss, off);
    if (lane == 0) rs[wid] = loss;
    __syncthreads();
    if (t == 0) {
        float s = rs[0];
#pragma unroll
        for (int w = 1; w < 8; w++) s += rs[w];
        g_partial[blockIdx.x] = s;
    }
}

__global__ void final_k(float* __restrict__ out) {
    float v = g_partial[threadIdx.x];
#pragma unroll
    for (int off = 16; off; off >>= 1)
        v += __shfl_xor_sync(0xffffffffu, v, off);
    if (threadIdx.x == 0) out[0] = v * (1.0f / (float)NB);
}

extern "C" void kernel_launch(void* const* d_in, const int* in_sizes, int n_in,
                              void* d_out, int out_size) {
    const float* o1 = (const float*)d_in[0];
    const float* o2 = (const float*)d_in[1];
    const float* o3 = (const float*)d_in[2];
    const float* o4 = (const float*)d_in[3];
    const float* os = (const float*)d_in[4];
    const int*   tg = (const int*)d_in[5];
    (void)in_sizes; (void)n_in; (void)out_size;

    row_kernel<<<NBLK, 256>>>(o1, o2, o3, o4, os, tg);
    reduce_kernel<<<RBLK, 256>>>();
    final_k<<<1, 32>>>((float*)d_out);
}

// round 8
// speedup vs baseline: 1.3188x; 1.3188x over previous
#include <cuda_runtime.h>
#include <math_constants.h>

// Warp-per-row fused multi-teacher KD loss.
// R7 = R5 (best known) + __ldcs streaming loads + mimic 0.25-fold + explicit
// ex2.approx. (R6 f32x2 experiment reverted: pack/unpack MOVs + 64-bit dep
// chains regressed 39.8 -> 46.7 us.)

namespace {
constexpr int NB = 8192;
constexpr int NC = 1000;
constexpr int NV4 = 250;
constexpr int NBLK = NB / 8;                       // 1024 row_kernel blocks
constexpr int RBLK = 32;
constexpr float L2E  = 1.4426950408889634f;        // log2(e)
constexpr float C20  = 1.4426950408889634f / 20.0f;
constexpr float C80  = 1.4426950408889634f / 80.0f; // for s4 = 4*zm
constexpr float CTHR = 1.4426950408889634f / 6.0f;
}

__device__ float g_rowbuf[NB * 16];
__device__ float g_bmin[NBLK];
__device__ float g_bmax[NBLK];
__device__ float g_partial[RBLK];

__device__ __forceinline__ float ex2(float x) {
    float r; asm("ex2.approx.ftz.f32 %0, %1;" : "=f"(r) : "f"(x)); return r;
}

__global__ __launch_bounds__(256, 4) void row_kernel(
    const float* __restrict__ o1, const float* __restrict__ o2,
    const float* __restrict__ o3, const float* __restrict__ o4,
    const float* __restrict__ os, const int* __restrict__ tgts)
{
    __shared__ float s_min[8], s_max[8];

    const int lane = threadIdx.x & 31;
    const int wid  = threadIdx.x >> 5;
    const int row  = blockIdx.x * 8 + wid;
    const size_t base = (size_t)row * NC;

    const float4* A  = reinterpret_cast<const float4*>(o1 + base) + lane;
    const float4* B  = reinterpret_cast<const float4*>(o2 + base) + lane;
    const float4* C  = reinterpret_cast<const float4*>(o3 + base) + lane;
    const float4* D4 = reinterpret_cast<const float4*>(o4 + base) + lane;
    const float4* S  = reinterpret_cast<const float4*>(os + base) + lane;

    float E[5]  = {0, 0, 0, 0, 0};
    float D[5]  = {0, 0, 0, 0, 0};
    float Es1 = 0.0f, EsT = 0.0f;
    float m1[4];                                   // teacher maxes
#pragma unroll
    for (int b = 0; b < 4; b++) m1[b] = -CUDART_INF_F;
    float ms4 = -CUDART_INF_F;                     // max of s4 = 4*zm

    auto body = [&](float4 va, float4 vb, float4 vc, float4 vd, float4 vs) {
        const float za[4]  = { va.x, va.y, va.z, va.w };
        const float zb[4]  = { vb.x, vb.y, vb.z, vb.w };
        const float zc[4]  = { vc.x, vc.y, vc.z, vc.w };
        const float zd[4]  = { vd.x, vd.y, vd.z, vd.w };
        const float zs4[4] = { vs.x, vs.y, vs.z, vs.w };
#pragma unroll
        for (int j = 0; j < 4; j++) {
            const float zs = zs4[j];
            Es1 += ex2(zs * L2E);
            EsT += ex2(zs * C20);
            const float s4 = (za[j] + zb[j]) + (zc[j] + zd[j]);   // 4*mimic
            const float zz[4] = { za[j], zb[j], zc[j], zd[j] };
#pragma unroll
            for (int b = 0; b < 4; b++) {
                const float z = zz[b];
                const float e = ex2(z * C20);
                E[b] += e;
                D[b]  = fmaf(e, z - zs, D[b]);
                m1[b] = fmaxf(m1[b], z);
            }
            // mimic branch via s4 (zm = 0.25*s4, scaling exact)
            const float em = ex2(s4 * C80);
            E[4] += em;
            D[4]  = fmaf(em, fmaf(s4, 0.25f, -zs), D[4]);
            ms4   = fmaxf(ms4, s4);
        }
    };

#pragma unroll 1
    for (int k = 0; k < 7; k++) {
        const int o = k * 32;
        body(__ldcs(A + o), __ldcs(B + o), __ldcs(C + o),
             __ldcs(D4 + o), __ldcs(S + o));
    }
    if (lane < NV4 - 224)                          // tail: idx = 224+lane < 250
        body(__ldcs(A + 224), __ldcs(B + 224), __ldcs(C + 224),
             __ldcs(D4 + 224), __ldcs(S + 224));

    // target logits: lane 0 gathers (L2 hot), then broadcast
    const int tg = tgts[row];
    float g0 = 0, g1 = 0, g2 = 0, g3 = 0, zst = 0;
    if (lane == 0) {
        g0 = o1[base + tg]; g1 = o2[base + tg];
        g2 = o3[base + tg]; g3 = o4[base + tg];
        zst = os[base + tg];
    }

    // warp reduction: 12 sums + 5 maxes
#pragma unroll
    for (int off = 16; off; off >>= 1) {
#pragma unroll
        for (int b = 0; b < 5; b++) {
            E[b] += __shfl_xor_sync(0xffffffffu, E[b], off);
            D[b] += __shfl_xor_sync(0xffffffffu, D[b], off);
        }
#pragma unroll
        for (int b = 0; b < 4; b++)
            m1[b] = fmaxf(m1[b], __shfl_xor_sync(0xffffffffu, m1[b], off));
        ms4 = fmaxf(ms4, __shfl_xor_sync(0xffffffffu, ms4, off));
        Es1 += __shfl_xor_sync(0xffffffffu, Es1, off);
        EsT += __shfl_xor_sync(0xffffffffu, EsT, off);
    }
    const float m1m[5] = { m1[0], m1[1], m1[2], m1[3], ms4 * 0.25f };

    g0  = __shfl_sync(0xffffffffu, g0, 0);
    g1  = __shfl_sync(0xffffffffu, g1, 0);
    g2  = __shfl_sync(0xffffffffu, g2, 0);
    g3  = __shfl_sync(0xffffffffu, g3, 0);
    zst = __shfl_sync(0xffffffffu, zst, 0);
    const float g4 = ((g0 + g1) + (g2 + g3)) * 0.25f;
    const float g[5] = { g0, g1, g2, g3, g4 };

    // rare re-pass: only when some branch's max equals its target logit
    float m2[5] = { -CUDART_INF_F, -CUDART_INF_F, -CUDART_INF_F,
                    -CUDART_INF_F, -CUDART_INF_F };
    bool need = false;
#pragma unroll
    for (int b = 0; b < 5; b++) need |= (m1m[b] == g[b]);
    if (need) {                                   // warp-uniform, rare
        float n1[5], n2[5];
#pragma unroll
        for (int b = 0; b < 5; b++) { n1[b] = -CUDART_INF_F; n2[b] = -CUDART_INF_F; }
        auto top2 = [&](float4 va, float4 vb, float4 vc, float4 vd) {
            const float za[4] = { va.x, va.y, va.z, va.w };
            const float zb[4] = { vb.x, vb.y, vb.z, vb.w };
            const float zc[4] = { vc.x, vc.y, vc.z, vc.w };
            const float zd[4] = { vd.x, vd.y, vd.z, vd.w };
#pragma unroll
            for (int j = 0; j < 4; j++) {
                const float s4 = (za[j] + zb[j]) + (zc[j] + zd[j]);
                const float zz[5] = { za[j], zb[j], zc[j], zd[j], s4 * 0.25f };
#pragma unroll
                for (int b = 0; b < 5; b++) {
                    const float z = zz[b];
                    n2[b] = fmaxf(n2[b], fminf(n1[b], z));
                    n1[b] = fmaxf(n1[b], z);
                }
            }
        };
#pragma unroll 1
        for (int k = 0; k < 7; k++) {
            const int o = k * 32;
            top2(A[o], B[o], C[o], D4[o]);
        }
        if (lane < NV4 - 224)
            top2(A[224], B[224], C[224], D4[224]);
#pragma unroll
        for (int off = 16; off; off >>= 1) {
#pragma unroll
            for (int b = 0; b < 5; b++) {
                float a1 = __shfl_xor_sync(0xffffffffu, n1[b], off);
                float a2 = __shfl_xor_sync(0xffffffffu, n2[b], off);
                n2[b] = fmaxf(n2[b], fminf(n1[b], a1));
                n2[b] = fmaxf(n2[b], a2);
                n1[b] = fmaxf(n1[b], a1);
            }
        }
#pragma unroll
        for (int b = 0; b < 5; b++) m2[b] = n2[b];
    }

    if (lane == 0) {
        float te[5], ts = 0.0f;
#pragma unroll
        for (int b = 0; b < 5; b++) {
            const float mg = (m1m[b] == g[b]) ? (m1m[b] - m2[b]) : 0.0f;
            te[b] = ex2(mg * CTHR);
            ts += te[b];
        }
        const float invts = 1.0f / ts;

        const float CE   = __logf(Es1) - zst;
        const float lseT = __logf(EsT);

        float rb[16];
        rb[0] = CE;
#pragma unroll
        for (int b = 0; b < 5; b++) {
            const float iE = 1.0f / E[b];
            const float KD = 20.0f * D[b] * iE + 400.0f * (lseT - __logf(E[b]));
            rb[1 + b]  = te[b] * invts;
            rb[6 + b]  = g[b];
            rb[11 + b] = KD;
        }
        float4* out4 = reinterpret_cast<float4*>(g_rowbuf + (size_t)row * 16);
        out4[0] = make_float4(rb[0],  rb[1],  rb[2],  rb[3]);
        out4[1] = make_float4(rb[4],  rb[5],  rb[6],  rb[7]);
        out4[2] = make_float4(rb[8],  rb[9],  rb[10], rb[11]);
        out4[3] = make_float4(rb[12], rb[13], rb[14], rb[15]);

        s_min[wid] = fminf(fminf(g[0], g[1]), fminf(g[2], g[3]));
        s_max[wid] = fmaxf(fmaxf(m1m[0], m1m[1]), fmaxf(m1m[2], m1m[3]));
    }
    __syncthreads();
    if (threadIdx.x == 0) {
        float mn = s_min[0], mx = s_max[0];
#pragma unroll
        for (int w = 1; w < 8; w++) { mn = fminf(mn, s_min[w]); mx = fmaxf(mx, s_max[w]); }
        g_bmin[blockIdx.x] = mn;
        g_bmax[blockIdx.x] = mx;
    }
}

__global__ __launch_bounds__(256) void reduce_kernel() {
    __shared__ float sm[8], sx[8], rs[8];
    const int t = threadIdx.x, lane = t & 31, wid = t >> 5;

    float mn = CUDART_INF_F, mx = -CUDART_INF_F;
#pragma unroll
    for (int i = 0; i < NBLK / 256; i++) {
        mn = fminf(mn, g_bmin[t + i * 256]);
        mx = fmaxf(mx, g_bmax[t + i * 256]);
    }
#pragma unroll
    for (int off = 16; off; off >>= 1) {
        mn = fminf(mn, __shfl_xor_sync(0xffffffffu, mn, off));
        mx = fmaxf(mx, __shfl_xor_sync(0xffffffffu, mx, off));
    }
    if (lane == 0) { sm[wid] = mn; sx[wid] = mx; }
    __syncthreads();
    float Cv = sm[0], Mv = sx[0];
#pragma unroll
    for (int w = 1; w < 8; w++) { Cv = fminf(Cv, sm[w]); Mv = fmaxf(Mv, sx[w]); }

    const float shift = (Cv < 0.0f) ? (-Cv + 1e-5f) : 0.0f;
    const float inv   = 1.0f / (Mv + shift);

    const int row = blockIdx.x * 256 + t;
    const float* r = g_rowbuf + (size_t)row * 16;
    float4 q0 = *reinterpret_cast<const float4*>(r);
    float4 q1 = *reinterpret_cast<const float4*>(r + 4);
    float4 q2 = *reinterpret_cast<const float4*>(r + 8);
    float4 q3 = *reinterpret_cast<const float4*>(r + 12);
    const float a[16] = { q0.x,q0.y,q0.z,q0.w, q1.x,q1.y,q1.z,q1.w,
                          q2.x,q2.y,q2.z,q2.w, q3.x,q3.y,q3.z,q3.w };
    const float CE = a[0];
    float loss = 0.0f;
#pragma unroll
    for (int b = 0; b < 5; b++) {
        const float w2 = (a[6 + b] + shift) * inv;
        loss += a[1 + b] * ((1.0f - w2) * CE + w2 * a[11 + b]);
    }
#pragma unroll
    for (int off = 16; off; off >>= 1)
        loss += __shfl_xor_sync(0xffffffffu, loss, off);
    if (lane == 0) rs[wid] = loss;
    __syncthreads();
    if (t == 0) {
        float s = rs[0];
#pragma unroll
        for (int w = 1; w < 8; w++) s += rs[w];
        g_partial[blockIdx.x] = s;
    }
}

__global__ void final_k(float* __restrict__ out) {
    float v = g_partial[threadIdx.x];
#pragma unroll
    for (int off = 16; off; off >>= 1)
        v += __shfl_xor_sync(0xffffffffu, v, off);
    if (threadIdx.x == 0) out[0] = v * (1.0f / (float)NB);
}

extern "C" void kernel_launch(void* const* d_in, const int* in_sizes, int n_in,
                              void* d_out, int out_size) {
    const float* o1 = (const float*)d_in[0];
    const float* o2 = (const float*)d_in[1];
    const float* o3 = (const float*)d_in[2];
    const float* o4 = (const float*)d_in[3];
    const float* os = (const float*)d_in[4];
    const int*   tg = (const int*)d_in[5];
    (void)in_sizes; (void)n_in; (void)out_size;

    row_kernel<<<NBLK, 256>>>(o1, o2, o3, o4, os, tg);
    reduce_kernel<<<RBLK, 256>>>();
    final_k<<<1, 32>>>((float*)d_out);
}